// round 6
// baseline (speedup 1.0000x reference)
#include <cuda_runtime.h>
#include <math.h>

#define BTOT 512
#define NMEM 30
#define HW 1024
#define NGTH_ 15
#define TPB 640
#define NWARP 20

typedef unsigned long long u64;

__device__ __forceinline__ u64 dup2f(float v) {
    u64 r; asm("mov.b64 %0, {%1, %1};" : "=l"(r) : "f"(v)); return r;
}
__device__ __forceinline__ void fma2(u64& d, u64 a, u64 b) {
    asm("fma.rn.f32x2 %0, %1, %2, %0;" : "+l"(d) : "l"(a), "l"(b));
}
__device__ __forceinline__ float2 unp2(u64 v) {
    float lo, hi; asm("mov.b64 {%0, %1}, %2;" : "=f"(lo), "=f"(hi) : "l"(v));
    return make_float2(lo, hi);
}

__device__ float g_inp6[(size_t)BTOT * 6 * HW];
__device__ float g_cst[(size_t)BTOT * 8];

// ---------------------------------------------------------------------------
// Kernel 1: per-image statistics
// ---------------------------------------------------------------------------
__global__ __launch_bounds__(256) void stats_kernel(
    const float* __restrict__ ts,
    const float* __restrict__ ptm,
    const float* __restrict__ pmt,
    const float* __restrict__ piou,
    const void* __restrict__ mask_raw)
{
    const int b = blockIdx.x;
    const int tid = threadIdx.x;
    const int lane = tid & 31;
    const int wid = tid >> 5;

    __shared__ float mf[NMEM], ow[NMEM];
    __shared__ float pmax[NMEM];
    __shared__ float warpmax[8];
    __shared__ float sc[16];

    unsigned int w0 = *(const unsigned int*)mask_raw;
    int mode = (w0 == 1u) ? 1 : ((w0 == 0x3F800000u) ? 2 : 0);

    if (tid == 0) {
        float run = 0.f, ca = 0.f, cg = 0.f, co = 0.f;
        for (int m = 0; m < NMEM; ++m) {
            int idx = b * NMEM + m;
            float f;
            if (mode == 1)      f = (((const int*)mask_raw)[idx] != 0) ? 1.f : 0.f;
            else if (mode == 2) f = (((const float*)mask_raw)[idx] != 0.f) ? 1.f : 0.f;
            else                f = (((const unsigned char*)mask_raw)[idx] != 0) ? 1.f : 0.f;
            run += f;
            float rank = run - 1.f;
            float g = (rank < (float)NGTH_) ? f : 0.f;
            float o = f - g;
            mf[m] = f; ow[m] = o;
            ca += f; cg += g; co += o;
        }
        sc[7] = ca; sc[8] = cg; sc[9] = co;
    }

    float tmax = -INFINITY;
    const float* tsb = ts + (size_t)b * HW;
    for (int p = tid; p < HW; p += 256) tmax = fmaxf(tmax, tsb[p]);
    #pragma unroll
    for (int off = 16; off > 0; off >>= 1)
        tmax = fmaxf(tmax, __shfl_xor_sync(0xffffffffu, tmax, off));
    if (lane == 0) warpmax[wid] = tmax;

    const float* ptmb = ptm + (size_t)b * NMEM * HW;
    for (int m = wid; m < NMEM; m += 8) {
        float mx = -INFINITY;
        const float* pr = ptmb + (size_t)m * HW;
        for (int p = lane; p < HW; p += 32) mx = fmaxf(mx, pr[p]);
        #pragma unroll
        for (int off = 16; off > 0; off >>= 1)
            mx = fmaxf(mx, __shfl_xor_sync(0xffffffffu, mx, off));
        if (lane == 0) pmax[m] = mx;
    }
    __syncthreads();

    if (wid == 0) {
        float v = (lane < 8) ? warpmax[lane] : -INFINITY;
        #pragma unroll
        for (int off = 4; off > 0; off >>= 1)
            v = fmaxf(v, __shfl_xor_sync(0xffffffffu, v, off));
        if (lane == 0) sc[0] = v;
    }
    if (wid == 1) {
        float v  = (lane < NMEM) ? pmax[lane] : 0.f;
        float fa = (lane < NMEM) ? mf[lane] : 0.f;
        float fo = (lane < NMEM) ? ow[lane] : 0.f;
        float fg = fa - fo;
        float sa = v * fa, ssa = v * v * fa;
        float sg = v * fg, ssg = v * v * fg;
        float so = v * fo, sso = v * v * fo;
        #pragma unroll
        for (int off = 16; off > 0; off >>= 1) {
            sa  += __shfl_xor_sync(0xffffffffu, sa, off);
            ssa += __shfl_xor_sync(0xffffffffu, ssa, off);
            sg  += __shfl_xor_sync(0xffffffffu, sg, off);
            ssg += __shfl_xor_sync(0xffffffffu, ssg, off);
            so  += __shfl_xor_sync(0xffffffffu, so, off);
            sso += __shfl_xor_sync(0xffffffffu, sso, off);
        }
        if (lane == 0) {
            float ca = sc[7], cg = sc[8], co = sc[9];
            float mA = sa / ca; sc[1] = mA; sc[2] = sqrtf(fmaxf(ssa / ca - mA * mA, 0.f));
            float mG = sg / cg; sc[3] = mG; sc[4] = sqrtf(fmaxf(ssg / cg - mG * mG, 0.f));
            float mO = so / co; sc[5] = mO; sc[6] = sqrtf(fmaxf(sso / co - mO * mO, 0.f));
        }
    }
    __syncthreads();

    if (tid == 0) {
        float* c = g_cst + (size_t)b * 8;
        c[0] = sc[0]; c[1] = piou[b];
        c[2] = sc[1]; c[3] = sc[2]; c[4] = sc[3];
        c[5] = sc[4]; c[6] = sc[5]; c[7] = sc[6];
    }

    float* ob = g_inp6 + (size_t)b * 6 * HW;
    const float* pmtb = pmt + (size_t)b * NMEM * HW;
    const float ca = sc[7], co = sc[9];

    for (int p = tid; p < HW; p += 256) {
        float sa = 0, ssa = 0, sg = 0, ssg = 0, so = 0, sso = 0;
        #pragma unroll 5
        for (int m = 0; m < NMEM; ++m) {
            float v = pmtb[(size_t)m * HW + p];
            float fa = mf[m], fo = ow[m];
            sa += v * fa; ssa += v * v * fa;
            if (m < NGTH_) { sg += v; ssg += v * v; }
            so += v * fo; sso += v * v * fo;
        }
        float mA = sa / ca, sA = sqrtf(fmaxf(ssa / ca - mA * mA, 0.f));
        float mG = sg * (1.f / NGTH_), sG = sqrtf(fmaxf(ssg * (1.f / NGTH_) - mG * mG, 0.f));
        float mO = so / co, sO = sqrtf(fmaxf(sso / co - mO * mO, 0.f));
        ob[0 * HW + p] = mA;
        ob[1 * HW + p] = sA;
        ob[2 * HW + p] = mG;
        ob[3 * HW + p] = sG;
        ob[4 * HW + p] = mO;
        ob[5 * HW + p] = sO;
    }
}

// ---------------------------------------------------------------------------
// Fused CNN. Warp = oc-quad-pair; lanes = column-contiguous.
// smem float layout (stride 18 tiles, input stride 34):
//   OA  [0,     14976)  conv1 input 6x32x34=6528 / x2 64x13x18=14976
//   OB  [14976, 32256)  x1 64x15x18=17280        / x3 64x11x18=12672
//   OWT [32256, 50688)  weights (32 pairs x 32 ic x 18)
//   OE  [50688, 50816)  folded BN scale[64]+bias[64]
//   ORED[50816, 50848)
// ---------------------------------------------------------------------------
#define OA 0
#define OB 14976
#define OWT 32256
#define OE 50688
#define ORED 50816
#define SMEM_FLOATS 50848
#define SMEM_BYTES (SMEM_FLOATS * 4)
#define S_T 18

__device__ __forceinline__ void accrow(
    u64& aA, u64& aB, const u64* __restrict__ wA, const u64* __restrict__ wB,
    const u64* ra, const u64* rb, const u64* rc)
{
    #pragma unroll
    for (int kx = 0; kx < 3; ++kx) {
        fma2(aA, wA[kx], ra[kx]);
        fma2(aA, wA[3 + kx], rb[kx]);
        fma2(aA, wA[6 + kx], rc[kx]);
        fma2(aB, wB[kx], ra[kx]);
        fma2(aB, wB[3 + kx], rb[kx]);
        fma2(aB, wB[6 + kx], rc[kx]);
    }
}

// 64->64 3x3 conv stage. Warp unit = (quad-pair, row-slab); lane = (sub-quad, col).
// RSEL=0: conv2 (NC=13, slabs {0,3,6,9,12} len {3,3,3,3,1})
// RSEL=1: conv3 (NC=11, slabs {0,3,5,7,9}  len {3,2,2,2,2})
template<int INCS, int OUTCS, int NC, int RSEL>
__device__ __forceinline__ void conv_stage(
    float* sm, int inOff, int outOff,
    const float* __restrict__ wsrc,
    const float* __restrict__ cbv, const float* __restrict__ gv,
    const float* __restrict__ bbv, const float* __restrict__ mv,
    const float* __restrict__ vv)
{
    const int tid = threadIdx.x;
    const int wid = tid >> 5;
    const int lane = tid & 31;
    const bool act = lane < 2 * NC;
    int subr = lane / NC; if (subr > 1) subr = 1;
    const int sub = subr;
    const int col = lane % NC;

    int r0k[2], nrk[2], qk[2];
    #pragma unroll
    for (int k = 0; k < 2; ++k) {
        int u = wid + NWARP * k;       // 40 units
        int qp = u / 5, rs = u % 5;
        if (RSEL == 0) { const int RS[5] = {0,3,6,9,12}, RN[5] = {3,3,3,3,1};
                         r0k[k] = RS[rs]; nrk[k] = RN[rs]; }
        else           { const int RS[5] = {0,3,5,7,9},  RN[5] = {3,2,2,2,2};
                         r0k[k] = RS[rs]; nrk[k] = RN[rs]; }
        qk[k] = 2 * qp + sub;
    }

    u64 acc[2][2][3];
    #pragma unroll
    for (int k = 0; k < 2; ++k)
        #pragma unroll
        for (int p = 0; p < 2; ++p)
            #pragma unroll
            for (int r = 0; r < 3; ++r) acc[k][p][r] = 0ull;

    for (int h = 0; h < 2; ++h) {
        __syncthreads();
        for (int i = tid; i < 64 * 32 * 9; i += TPB) {
            int oc = i / 288; int r = i - oc * 288;
            int icl = r / 9; int t = r - icl * 9;
            sm[OWT + ((oc >> 1) * 32 + icl) * 18 + t * 2 + (oc & 1)] =
                wsrc[oc * 576 + h * 288 + r];
        }
        if (h == 0 && tid < 64) {
            float s = gv[tid] * rsqrtf(vv[tid] + 1e-5f);
            sm[OE + tid] = s;
            sm[OE + 64 + tid] = s * (cbv[tid] - mv[tid]) + bbv[tid];
        }
        __syncthreads();

        #pragma unroll
        for (int k = 0; k < 2; ++k) {
            const int r0 = r0k[k], nr = nrk[k], quad = qk[k];
            const float* ibase = &sm[inOff + h * 32 * INCS + r0 * S_T + col];
            const u64* wbase = (const u64*)&sm[OWT];
            for (int icl = 0; icl < 32; ++icl) {
                const float* ib = ibase + icl * INCS;
                const u64* wA = wbase + (2 * quad * 32 + icl) * 9;
                const u64* wB = wA + 288;
                u64 ra[3], rb[3], rc[3];
                #pragma unroll
                for (int t = 0; t < 3; ++t) {
                    ra[t] = dup2f(ib[t]);
                    rb[t] = dup2f(ib[S_T + t]);
                    rc[t] = dup2f(ib[2 * S_T + t]);
                }
                accrow(acc[k][0][0], acc[k][1][0], wA, wB, ra, rb, rc);
                if (nr > 1) {
                    #pragma unroll
                    for (int t = 0; t < 3; ++t) ra[t] = dup2f(ib[3 * S_T + t]);
                    accrow(acc[k][0][1], acc[k][1][1], wA, wB, rb, rc, ra);
                }
                if (nr > 2) {
                    #pragma unroll
                    for (int t = 0; t < 3; ++t) rb[t] = dup2f(ib[4 * S_T + t]);
                    accrow(acc[k][0][2], acc[k][1][2], wA, wB, rc, ra, rb);
                }
            }
        }
    }

    #pragma unroll
    for (int k = 0; k < 2; ++k) {
        if (act) {
            int oc0 = 4 * qk[k];
            float s0 = sm[OE + oc0],     b0 = sm[OE + 64 + oc0];
            float s1 = sm[OE + oc0 + 1], b1 = sm[OE + 64 + oc0 + 1];
            float s2 = sm[OE + oc0 + 2], b2 = sm[OE + 64 + oc0 + 2];
            float s3 = sm[OE + oc0 + 3], b3 = sm[OE + 64 + oc0 + 3];
            #pragma unroll
            for (int rr = 0; rr < 3; ++rr) {
                if (rr < nrk[k]) {
                    int y = r0k[k] + rr;
                    float2 vA = unp2(acc[k][0][rr]);
                    float2 vB = unp2(acc[k][1][rr]);
                    sm[outOff + (oc0    ) * OUTCS + y * S_T + col] = fmaxf(s0 * vA.x + b0, 0.f);
                    sm[outOff + (oc0 + 1) * OUTCS + y * S_T + col] = fmaxf(s1 * vA.y + b1, 0.f);
                    sm[outOff + (oc0 + 2) * OUTCS + y * S_T + col] = fmaxf(s2 * vB.x + b2, 0.f);
                    sm[outOff + (oc0 + 3) * OUTCS + y * S_T + col] = fmaxf(s3 * vB.y + b3, 0.f);
                }
            }
        }
    }
}

__global__ __launch_bounds__(TPB, 1) void cnn_kernel(
    const float* __restrict__ w1, const float* __restrict__ cb1,
    const float* __restrict__ g1, const float* __restrict__ bb1,
    const float* __restrict__ m1, const float* __restrict__ v1,
    const float* __restrict__ w2, const float* __restrict__ cb2,
    const float* __restrict__ g2, const float* __restrict__ bb2,
    const float* __restrict__ m2, const float* __restrict__ v2,
    const float* __restrict__ w3, const float* __restrict__ cb3,
    const float* __restrict__ g3, const float* __restrict__ bb3,
    const float* __restrict__ m3, const float* __restrict__ v3,
    const float* __restrict__ w4, const float* __restrict__ cb4,
    float* __restrict__ out)
{
    extern __shared__ float sm[];
    const int b = blockIdx.x;
    const int tid = threadIdx.x;
    const int wid = tid >> 5;
    const int lane = tid & 31;

    // ---------------- prologue: input (stride 34), conv1 weights (pair layout), E1 ----------------
    {
        const float* src = g_inp6 + (size_t)b * 6 * HW;
        for (int i = tid; i < 6 * HW; i += TPB) {
            int c = i >> 10; int rem = i & 1023;
            int r = rem >> 5; int x = rem & 31;
            sm[OA + c * 1088 + r * 34 + x] = src[i];
        }
        for (int i = tid; i < 64 * 6 * 9; i += TPB) {
            int oc = i / 54; int r = i - oc * 54;
            int c = r / 9; int t = r - c * 9;
            sm[OWT + ((oc >> 1) * 6 + c) * 18 + t * 2 + (oc & 1)] =
                w1[oc * 126 + (c + 2) * 9 + t];
        }
        if (tid < 64) {
            const float* cst = g_cst + (size_t)b * 8;
            float extra = 0.f;
            #pragma unroll
            for (int j = 0; j < 8; ++j) {
                int ic = (j < 2) ? j : (j + 6);
                const float* wb = w1 + tid * 126 + ic * 9;
                float s9 = 0.f;
                #pragma unroll
                for (int t = 0; t < 9; ++t) s9 += wb[t];
                extra += cst[j] * s9;
            }
            float s = g1[tid] * rsqrtf(v1[tid] + 1e-5f);
            sm[OE + tid] = s;
            sm[OE + 64 + tid] = s * (extra + cb1[tid] - m1[tid]) + bb1[tid];
        }
    }
    __syncthreads();

    // ---------------- stage 1: conv1 (6ic) + bn + relu + 2x2 pool -> x1 (OB) ----------------
    // warp unit = (quad-pair, pooled row); lanes = 2 subs x 15 pooled cols. 120 units = 6/warp.
    {
        const bool act = lane < 30;
        int subr = lane / 15; if (subr > 1) subr = 1;
        const int pcol = lane % 15;
        const int c0 = 2 * pcol;

        #pragma unroll
        for (int k = 0; k < 6; ++k) {
            int u = wid + NWARP * k;
            int qp = u / 15, prow = u % 15;
            int quad = 2 * qp + subr;
            int r0 = 2 * prow;

            u64 acc[2][4];
            #pragma unroll
            for (int p = 0; p < 2; ++p)
                #pragma unroll
                for (int q = 0; q < 4; ++q) acc[p][q] = 0ull;

            for (int ch = 0; ch < 6; ++ch) {
                const float* ib = &sm[OA + ch * 1088 + r0 * 34 + c0];
                u64 d[4][4];
                #pragma unroll
                for (int rr = 0; rr < 4; ++rr) {
                    float2 a0 = *(const float2*)(ib + rr * 34);
                    float2 a1 = *(const float2*)(ib + rr * 34 + 2);
                    d[rr][0] = dup2f(a0.x); d[rr][1] = dup2f(a0.y);
                    d[rr][2] = dup2f(a1.x); d[rr][3] = dup2f(a1.y);
                }
                const u64* wA = (const u64*)&sm[OWT] + (2 * quad * 6 + ch) * 9;
                const u64* wB = wA + 54;
                #pragma unroll
                for (int ky = 0; ky < 3; ++ky)
                    #pragma unroll
                    for (int kx = 0; kx < 3; ++kx) {
                        u64 a = wA[ky * 3 + kx], bq = wB[ky * 3 + kx];
                        #pragma unroll
                        for (int dy = 0; dy < 2; ++dy)
                            #pragma unroll
                            for (int dx = 0; dx < 2; ++dx) {
                                fma2(acc[0][dy * 2 + dx], a, d[dy + ky][dx + kx]);
                                fma2(acc[1][dy * 2 + dx], bq, d[dy + ky][dx + kx]);
                            }
                    }
            }
            if (act) {
                int oc0 = 4 * quad;
                #pragma unroll
                for (int p = 0; p < 2; ++p) {
                    float sA = sm[OE + oc0 + 2 * p],     bA = sm[OE + 64 + oc0 + 2 * p];
                    float sB = sm[OE + oc0 + 2 * p + 1], bB = sm[OE + 64 + oc0 + 2 * p + 1];
                    float2 q0 = unp2(acc[p][0]), q1 = unp2(acc[p][1]);
                    float2 q2 = unp2(acc[p][2]), q3 = unp2(acc[p][3]);
                    float lo = fmaxf(fmaxf(fmaxf(sA * q0.x + bA, 0.f), fmaxf(sA * q1.x + bA, 0.f)),
                                     fmaxf(fmaxf(sA * q2.x + bA, 0.f), fmaxf(sA * q3.x + bA, 0.f)));
                    float hi = fmaxf(fmaxf(fmaxf(sB * q0.y + bB, 0.f), fmaxf(sB * q1.y + bB, 0.f)),
                                     fmaxf(fmaxf(sB * q2.y + bB, 0.f), fmaxf(sB * q3.y + bB, 0.f)));
                    sm[OB + (oc0 + 2 * p) * 270 + prow * S_T + pcol] = lo;
                    sm[OB + (oc0 + 2 * p + 1) * 270 + prow * S_T + pcol] = hi;
                }
            }
        }
    }

    // ---------------- stage 2: conv2 (15x15 -> 13x13), OB -> OA ----------------
    conv_stage<270, 234, 13, 0>(sm, OB, OA, w2, cb2, g2, bb2, m2, v2);

    // ---------------- stage 3: conv3 (13x13 -> 11x11), OA -> OB ----------------
    conv_stage<234, 198, 11, 1>(sm, OA, OB, w3, cb3, g3, bb3, m3, v3);

    // ---------------- stage 4: conv4 (64->1, 11x11 -> 9x9) + global max ----------------
    __syncthreads();
    for (int i = tid; i < 576; i += TPB) sm[OWT + i] = w4[i];
    __syncthreads();

    float lmax = -INFINITY;
    if (tid < 81) {
        int y = tid / 9, x = tid - (tid / 9) * 9;
        float a = 0.f;
        for (int ic = 0; ic < 64; ++ic) {
            const float* ib = &sm[OB + ic * 198 + y * S_T + x];
            const float* wb = &sm[OWT + ic * 9];
            #pragma unroll
            for (int ky = 0; ky < 3; ++ky)
                #pragma unroll
                for (int kx = 0; kx < 3; ++kx)
                    a += ib[ky * S_T + kx] * wb[ky * 3 + kx];
        }
        lmax = a;
    }
    #pragma unroll
    for (int off = 16; off > 0; off >>= 1)
        lmax = fmaxf(lmax, __shfl_xor_sync(0xffffffffu, lmax, off));
    if (lane == 0) sm[ORED + wid] = lmax;
    __syncthreads();
    if (tid < 32) {
        float v = (tid < NWARP) ? sm[ORED + tid] : -INFINITY;
        #pragma unroll
        for (int off = 16; off > 0; off >>= 1)
            v = fmaxf(v, __shfl_xor_sync(0xffffffffu, v, off));
        if (tid == 0) out[b] = v + cb4[0];
    }
}

// ---------------------------------------------------------------------------
extern "C" void kernel_launch(void* const* d_in, const int* in_sizes, int n_in,
                              void* d_out, int out_size)
{
    cudaFuncSetAttribute(cnn_kernel, cudaFuncAttributeMaxDynamicSharedMemorySize, SMEM_BYTES);

    stats_kernel<<<BTOT, 256>>>(
        (const float*)d_in[0],   // target_scores
        (const float*)d_in[1],   // ptm
        (const float*)d_in[2],   // pmt
        (const float*)d_in[3],   // predicted_iou
        d_in[4]);                // mem_mask (dtype auto-detected)

    cnn_kernel<<<BTOT, TPB, SMEM_BYTES>>>(
        (const float*)d_in[5],  (const float*)d_in[6],
        (const float*)d_in[7],  (const float*)d_in[8],
        (const float*)d_in[9],  (const float*)d_in[10],
        (const float*)d_in[11], (const float*)d_in[12],
        (const float*)d_in[13], (const float*)d_in[14],
        (const float*)d_in[15], (const float*)d_in[16],
        (const float*)d_in[17], (const float*)d_in[18],
        (const float*)d_in[19], (const float*)d_in[20],
        (const float*)d_in[21], (const float*)d_in[22],
        (const float*)d_in[23], (const float*)d_in[24],
        (float*)d_out);
}

// round 7
// speedup vs baseline: 1.0017x; 1.0017x over previous
#include <cuda_runtime.h>
#include <math.h>

#define BTOT 512
#define NMEM 30
#define HW 1024
#define NGTH_ 15
#define TPB 640
#define NWARP 20

typedef unsigned long long u64;

__device__ __forceinline__ u64 dup2f(float v) {
    u64 r; asm("mov.b64 %0, {%1, %1};" : "=l"(r) : "f"(v)); return r;
}
__device__ __forceinline__ void fma2(u64& d, u64 a, u64 b) {
    asm("fma.rn.f32x2 %0, %1, %2, %0;" : "+l"(d) : "l"(a), "l"(b));
}
__device__ __forceinline__ float2 unp2(u64 v) {
    float lo, hi; asm("mov.b64 {%0, %1}, %2;" : "=f"(lo), "=f"(hi) : "l"(v));
    return make_float2(lo, hi);
}

__device__ float g_inp6[(size_t)BTOT * 6 * HW];
__device__ float g_cst[(size_t)BTOT * 8];

// ---------------------------------------------------------------------------
// Kernel 1: per-image statistics
// ---------------------------------------------------------------------------
__global__ __launch_bounds__(256) void stats_kernel(
    const float* __restrict__ ts,
    const float* __restrict__ ptm,
    const float* __restrict__ pmt,
    const float* __restrict__ piou,
    const void* __restrict__ mask_raw)
{
    const int b = blockIdx.x;
    const int tid = threadIdx.x;
    const int lane = tid & 31;
    const int wid = tid >> 5;

    __shared__ float mf[NMEM], ow[NMEM];
    __shared__ float pmax[NMEM];
    __shared__ float warpmax[8];
    __shared__ float sc[16];

    unsigned int w0 = *(const unsigned int*)mask_raw;
    int mode = (w0 == 1u) ? 1 : ((w0 == 0x3F800000u) ? 2 : 0);

    if (tid == 0) {
        float run = 0.f, ca = 0.f, cg = 0.f, co = 0.f;
        for (int m = 0; m < NMEM; ++m) {
            int idx = b * NMEM + m;
            float f;
            if (mode == 1)      f = (((const int*)mask_raw)[idx] != 0) ? 1.f : 0.f;
            else if (mode == 2) f = (((const float*)mask_raw)[idx] != 0.f) ? 1.f : 0.f;
            else                f = (((const unsigned char*)mask_raw)[idx] != 0) ? 1.f : 0.f;
            run += f;
            float rank = run - 1.f;
            float g = (rank < (float)NGTH_) ? f : 0.f;
            float o = f - g;
            mf[m] = f; ow[m] = o;
            ca += f; cg += g; co += o;
        }
        sc[7] = ca; sc[8] = cg; sc[9] = co;
    }

    float tmax = -INFINITY;
    const float* tsb = ts + (size_t)b * HW;
    for (int p = tid; p < HW; p += 256) tmax = fmaxf(tmax, tsb[p]);
    #pragma unroll
    for (int off = 16; off > 0; off >>= 1)
        tmax = fmaxf(tmax, __shfl_xor_sync(0xffffffffu, tmax, off));
    if (lane == 0) warpmax[wid] = tmax;

    const float* ptmb = ptm + (size_t)b * NMEM * HW;
    for (int m = wid; m < NMEM; m += 8) {
        float mx = -INFINITY;
        const float* pr = ptmb + (size_t)m * HW;
        for (int p = lane; p < HW; p += 32) mx = fmaxf(mx, pr[p]);
        #pragma unroll
        for (int off = 16; off > 0; off >>= 1)
            mx = fmaxf(mx, __shfl_xor_sync(0xffffffffu, mx, off));
        if (lane == 0) pmax[m] = mx;
    }
    __syncthreads();

    if (wid == 0) {
        float v = (lane < 8) ? warpmax[lane] : -INFINITY;
        #pragma unroll
        for (int off = 4; off > 0; off >>= 1)
            v = fmaxf(v, __shfl_xor_sync(0xffffffffu, v, off));
        if (lane == 0) sc[0] = v;
    }
    if (wid == 1) {
        float v  = (lane < NMEM) ? pmax[lane] : 0.f;
        float fa = (lane < NMEM) ? mf[lane] : 0.f;
        float fo = (lane < NMEM) ? ow[lane] : 0.f;
        float fg = fa - fo;
        float sa = v * fa, ssa = v * v * fa;
        float sg = v * fg, ssg = v * v * fg;
        float so = v * fo, sso = v * v * fo;
        #pragma unroll
        for (int off = 16; off > 0; off >>= 1) {
            sa  += __shfl_xor_sync(0xffffffffu, sa, off);
            ssa += __shfl_xor_sync(0xffffffffu, ssa, off);
            sg  += __shfl_xor_sync(0xffffffffu, sg, off);
            ssg += __shfl_xor_sync(0xffffffffu, ssg, off);
            so  += __shfl_xor_sync(0xffffffffu, so, off);
            sso += __shfl_xor_sync(0xffffffffu, sso, off);
        }
        if (lane == 0) {
            float ca = sc[7], cg = sc[8], co = sc[9];
            float mA = sa / ca; sc[1] = mA; sc[2] = sqrtf(fmaxf(ssa / ca - mA * mA, 0.f));
            float mG = sg / cg; sc[3] = mG; sc[4] = sqrtf(fmaxf(ssg / cg - mG * mG, 0.f));
            float mO = so / co; sc[5] = mO; sc[6] = sqrtf(fmaxf(sso / co - mO * mO, 0.f));
        }
    }
    __syncthreads();

    if (tid == 0) {
        float* c = g_cst + (size_t)b * 8;
        c[0] = sc[0]; c[1] = piou[b];
        c[2] = sc[1]; c[3] = sc[2]; c[4] = sc[3];
        c[5] = sc[4]; c[6] = sc[5]; c[7] = sc[6];
    }

    float* ob = g_inp6 + (size_t)b * 6 * HW;
    const float* pmtb = pmt + (size_t)b * NMEM * HW;
    const float ca = sc[7], co = sc[9];

    for (int p = tid; p < HW; p += 256) {
        float sa = 0, ssa = 0, sg = 0, ssg = 0, so = 0, sso = 0;
        #pragma unroll 5
        for (int m = 0; m < NMEM; ++m) {
            float v = pmtb[(size_t)m * HW + p];
            float fa = mf[m], fo = ow[m];
            sa += v * fa; ssa += v * v * fa;
            if (m < NGTH_) { sg += v; ssg += v * v; }
            so += v * fo; sso += v * v * fo;
        }
        float mA = sa / ca, sA = sqrtf(fmaxf(ssa / ca - mA * mA, 0.f));
        float mG = sg * (1.f / NGTH_), sG = sqrtf(fmaxf(ssg * (1.f / NGTH_) - mG * mG, 0.f));
        float mO = so / co, sO = sqrtf(fmaxf(sso / co - mO * mO, 0.f));
        ob[0 * HW + p] = mA;
        ob[1 * HW + p] = sA;
        ob[2 * HW + p] = mG;
        ob[3 * HW + p] = sG;
        ob[4 * HW + p] = mO;
        ob[5 * HW + p] = sO;
    }
}

// ---------------------------------------------------------------------------
// Fused CNN. Warp = oc-quad-pair; lanes = column-contiguous.
// smem float layout (stride 18 tiles, input stride 34):
//   OA  [0,     14976)  conv1 input 6x32x34=6528 / x2 64x13x18=14976
//   OB  [14976, 32256)  x1 64x15x18=17280        / x3 64x11x18=12672
//   OWT [32256, 50688)  weights (32 pairs x 32 ic x 18)
//   OE  [50688, 50816)  folded BN scale[64]+bias[64]
//   ORED[50816, 50848)
// ---------------------------------------------------------------------------
#define OA 0
#define OB 14976
#define OWT 32256
#define OE 50688
#define ORED 50816
#define SMEM_FLOATS 50848
#define SMEM_BYTES (SMEM_FLOATS * 4)
#define S_T 18

__device__ __forceinline__ void accrow(
    u64& aA, u64& aB, const u64* __restrict__ wA, const u64* __restrict__ wB,
    const u64* ra, const u64* rb, const u64* rc)
{
    #pragma unroll
    for (int kx = 0; kx < 3; ++kx) {
        fma2(aA, wA[kx], ra[kx]);
        fma2(aA, wA[3 + kx], rb[kx]);
        fma2(aA, wA[6 + kx], rc[kx]);
        fma2(aB, wB[kx], ra[kx]);
        fma2(aB, wB[3 + kx], rb[kx]);
        fma2(aB, wB[6 + kx], rc[kx]);
    }
}

// 64->64 3x3 conv stage. Warp unit = (quad-pair, row-slab); lane = (sub-quad, col).
// RSEL=0: conv2 (NC=13, slabs {0,3,6,9,12} len {3,3,3,3,1})
// RSEL=1: conv3 (NC=11, slabs {0,3,5,7,9}  len {3,2,2,2,2})
template<int INCS, int OUTCS, int NC, int RSEL>
__device__ __forceinline__ void conv_stage(
    float* sm, int inOff, int outOff,
    const float* __restrict__ wsrc,
    const float* __restrict__ cbv, const float* __restrict__ gv,
    const float* __restrict__ bbv, const float* __restrict__ mv,
    const float* __restrict__ vv)
{
    const int tid = threadIdx.x;
    const int wid = tid >> 5;
    const int lane = tid & 31;
    const bool act = lane < 2 * NC;
    int subr = lane / NC; if (subr > 1) subr = 1;
    const int sub = subr;
    const int col = lane % NC;

    int r0k[2], nrk[2], qk[2];
    #pragma unroll
    for (int k = 0; k < 2; ++k) {
        int u = wid + NWARP * k;       // 40 units
        int qp = u / 5, rs = u % 5;
        if (RSEL == 0) { const int RS[5] = {0,3,6,9,12}, RN[5] = {3,3,3,3,1};
                         r0k[k] = RS[rs]; nrk[k] = RN[rs]; }
        else           { const int RS[5] = {0,3,5,7,9},  RN[5] = {3,2,2,2,2};
                         r0k[k] = RS[rs]; nrk[k] = RN[rs]; }
        qk[k] = 2 * qp + sub;
    }

    u64 acc[2][2][3];
    #pragma unroll
    for (int k = 0; k < 2; ++k)
        #pragma unroll
        for (int p = 0; p < 2; ++p)
            #pragma unroll
            for (int r = 0; r < 3; ++r) acc[k][p][r] = 0ull;

    for (int h = 0; h < 2; ++h) {
        __syncthreads();
        for (int i = tid; i < 64 * 32 * 9; i += TPB) {
            int oc = i / 288; int r = i - oc * 288;
            int icl = r / 9; int t = r - icl * 9;
            sm[OWT + ((oc >> 1) * 32 + icl) * 18 + t * 2 + (oc & 1)] =
                wsrc[oc * 576 + h * 288 + r];
        }
        if (h == 0 && tid < 64) {
            float s = gv[tid] * rsqrtf(vv[tid] + 1e-5f);
            sm[OE + tid] = s;
            sm[OE + 64 + tid] = s * (cbv[tid] - mv[tid]) + bbv[tid];
        }
        __syncthreads();

        #pragma unroll
        for (int k = 0; k < 2; ++k) {
            const int r0 = r0k[k], nr = nrk[k], quad = qk[k];
            const float* ibase = &sm[inOff + h * 32 * INCS + r0 * S_T + col];
            const u64* wbase = (const u64*)&sm[OWT];
            for (int icl = 0; icl < 32; ++icl) {
                const float* ib = ibase + icl * INCS;
                const u64* wA = wbase + (2 * quad * 32 + icl) * 9;
                const u64* wB = wA + 288;
                u64 ra[3], rb[3], rc[3];
                #pragma unroll
                for (int t = 0; t < 3; ++t) {
                    ra[t] = dup2f(ib[t]);
                    rb[t] = dup2f(ib[S_T + t]);
                    rc[t] = dup2f(ib[2 * S_T + t]);
                }
                accrow(acc[k][0][0], acc[k][1][0], wA, wB, ra, rb, rc);
                if (nr > 1) {
                    #pragma unroll
                    for (int t = 0; t < 3; ++t) ra[t] = dup2f(ib[3 * S_T + t]);
                    accrow(acc[k][0][1], acc[k][1][1], wA, wB, rb, rc, ra);
                }
                if (nr > 2) {
                    #pragma unroll
                    for (int t = 0; t < 3; ++t) rb[t] = dup2f(ib[4 * S_T + t]);
                    accrow(acc[k][0][2], acc[k][1][2], wA, wB, rc, ra, rb);
                }
            }
        }
    }

    #pragma unroll
    for (int k = 0; k < 2; ++k) {
        if (act) {
            int oc0 = 4 * qk[k];
            float s0 = sm[OE + oc0],     b0 = sm[OE + 64 + oc0];
            float s1 = sm[OE + oc0 + 1], b1 = sm[OE + 64 + oc0 + 1];
            float s2 = sm[OE + oc0 + 2], b2 = sm[OE + 64 + oc0 + 2];
            float s3 = sm[OE + oc0 + 3], b3 = sm[OE + 64 + oc0 + 3];
            #pragma unroll
            for (int rr = 0; rr < 3; ++rr) {
                if (rr < nrk[k]) {
                    int y = r0k[k] + rr;
                    float2 vA = unp2(acc[k][0][rr]);
                    float2 vB = unp2(acc[k][1][rr]);
                    sm[outOff + (oc0    ) * OUTCS + y * S_T + col] = fmaxf(s0 * vA.x + b0, 0.f);
                    sm[outOff + (oc0 + 1) * OUTCS + y * S_T + col] = fmaxf(s1 * vA.y + b1, 0.f);
                    sm[outOff + (oc0 + 2) * OUTCS + y * S_T + col] = fmaxf(s2 * vB.x + b2, 0.f);
                    sm[outOff + (oc0 + 3) * OUTCS + y * S_T + col] = fmaxf(s3 * vB.y + b3, 0.f);
                }
            }
        }
    }
}

__global__ __launch_bounds__(TPB, 1) void cnn_kernel(
    const float* __restrict__ w1, const float* __restrict__ cb1,
    const float* __restrict__ g1, const float* __restrict__ bb1,
    const float* __restrict__ m1, const float* __restrict__ v1,
    const float* __restrict__ w2, const float* __restrict__ cb2,
    const float* __restrict__ g2, const float* __restrict__ bb2,
    const float* __restrict__ m2, const float* __restrict__ v2,
    const float* __restrict__ w3, const float* __restrict__ cb3,
    const float* __restrict__ g3, const float* __restrict__ bb3,
    const float* __restrict__ m3, const float* __restrict__ v3,
    const float* __restrict__ w4, const float* __restrict__ cb4,
    float* __restrict__ out)
{
    extern __shared__ float sm[];
    const int b = blockIdx.x;
    const int tid = threadIdx.x;
    const int wid = tid >> 5;
    const int lane = tid & 31;

    // ---------------- prologue: input (stride 34), conv1 weights (pair layout), E1 ----------------
    {
        const float* src = g_inp6 + (size_t)b * 6 * HW;
        for (int i = tid; i < 6 * HW; i += TPB) {
            int c = i >> 10; int rem = i & 1023;
            int r = rem >> 5; int x = rem & 31;
            sm[OA + c * 1088 + r * 34 + x] = src[i];
        }
        for (int i = tid; i < 64 * 6 * 9; i += TPB) {
            int oc = i / 54; int r = i - oc * 54;
            int c = r / 9; int t = r - c * 9;
            sm[OWT + ((oc >> 1) * 6 + c) * 18 + t * 2 + (oc & 1)] =
                w1[oc * 126 + (c + 2) * 9 + t];
        }
        if (tid < 64) {
            const float* cst = g_cst + (size_t)b * 8;
            float extra = 0.f;
            #pragma unroll
            for (int j = 0; j < 8; ++j) {
                int ic = (j < 2) ? j : (j + 6);
                const float* wb = w1 + tid * 126 + ic * 9;
                float s9 = 0.f;
                #pragma unroll
                for (int t = 0; t < 9; ++t) s9 += wb[t];
                extra += cst[j] * s9;
            }
            float s = g1[tid] * rsqrtf(v1[tid] + 1e-5f);
            sm[OE + tid] = s;
            sm[OE + 64 + tid] = s * (extra + cb1[tid] - m1[tid]) + bb1[tid];
        }
    }
    __syncthreads();

    // ---------------- stage 1: conv1 (6ic) + bn + relu + 2x2 pool -> x1 (OB) ----------------
    // warp unit = (quad-pair, pooled row); lanes = 2 subs x 15 pooled cols. 120 units = 6/warp.
    {
        const bool act = lane < 30;
        int subr = lane / 15; if (subr > 1) subr = 1;
        const int pcol = lane % 15;
        const int c0 = 2 * pcol;

        #pragma unroll
        for (int k = 0; k < 6; ++k) {
            int u = wid + NWARP * k;
            int qp = u / 15, prow = u % 15;
            int quad = 2 * qp + subr;
            int r0 = 2 * prow;

            u64 acc[2][4];
            #pragma unroll
            for (int p = 0; p < 2; ++p)
                #pragma unroll
                for (int q = 0; q < 4; ++q) acc[p][q] = 0ull;

            for (int ch = 0; ch < 6; ++ch) {
                const float* ib = &sm[OA + ch * 1088 + r0 * 34 + c0];
                u64 d[4][4];
                #pragma unroll
                for (int rr = 0; rr < 4; ++rr) {
                    float2 a0 = *(const float2*)(ib + rr * 34);
                    float2 a1 = *(const float2*)(ib + rr * 34 + 2);
                    d[rr][0] = dup2f(a0.x); d[rr][1] = dup2f(a0.y);
                    d[rr][2] = dup2f(a1.x); d[rr][3] = dup2f(a1.y);
                }
                const u64* wA = (const u64*)&sm[OWT] + (2 * quad * 6 + ch) * 9;
                const u64* wB = wA + 54;
                #pragma unroll
                for (int ky = 0; ky < 3; ++ky)
                    #pragma unroll
                    for (int kx = 0; kx < 3; ++kx) {
                        u64 a = wA[ky * 3 + kx], bq = wB[ky * 3 + kx];
                        #pragma unroll
                        for (int dy = 0; dy < 2; ++dy)
                            #pragma unroll
                            for (int dx = 0; dx < 2; ++dx) {
                                fma2(acc[0][dy * 2 + dx], a, d[dy + ky][dx + kx]);
                                fma2(acc[1][dy * 2 + dx], bq, d[dy + ky][dx + kx]);
                            }
                    }
            }
            if (act) {
                int oc0 = 4 * quad;
                #pragma unroll
                for (int p = 0; p < 2; ++p) {
                    float sA = sm[OE + oc0 + 2 * p],     bA = sm[OE + 64 + oc0 + 2 * p];
                    float sB = sm[OE + oc0 + 2 * p + 1], bB = sm[OE + 64 + oc0 + 2 * p + 1];
                    float2 q0 = unp2(acc[p][0]), q1 = unp2(acc[p][1]);
                    float2 q2 = unp2(acc[p][2]), q3 = unp2(acc[p][3]);
                    float lo = fmaxf(fmaxf(fmaxf(sA * q0.x + bA, 0.f), fmaxf(sA * q1.x + bA, 0.f)),
                                     fmaxf(fmaxf(sA * q2.x + bA, 0.f), fmaxf(sA * q3.x + bA, 0.f)));
                    float hi = fmaxf(fmaxf(fmaxf(sB * q0.y + bB, 0.f), fmaxf(sB * q1.y + bB, 0.f)),
                                     fmaxf(fmaxf(sB * q2.y + bB, 0.f), fmaxf(sB * q3.y + bB, 0.f)));
                    sm[OB + (oc0 + 2 * p) * 270 + prow * S_T + pcol] = lo;
                    sm[OB + (oc0 + 2 * p + 1) * 270 + prow * S_T + pcol] = hi;
                }
            }
        }
    }

    // ---------------- stage 2: conv2 (15x15 -> 13x13), OB -> OA ----------------
    conv_stage<270, 234, 13, 0>(sm, OB, OA, w2, cb2, g2, bb2, m2, v2);

    // ---------------- stage 3: conv3 (13x13 -> 11x11), OA -> OB ----------------
    conv_stage<234, 198, 11, 1>(sm, OA, OB, w3, cb3, g3, bb3, m3, v3);

    // ---------------- stage 4: conv4 (64->1, 11x11 -> 9x9) + global max ----------------
    __syncthreads();
    for (int i = tid; i < 576; i += TPB) sm[OWT + i] = w4[i];
    __syncthreads();

    float lmax = -INFINITY;
    if (tid < 81) {
        int y = tid / 9, x = tid - (tid / 9) * 9;
        float a = 0.f;
        for (int ic = 0; ic < 64; ++ic) {
            const float* ib = &sm[OB + ic * 198 + y * S_T + x];
            const float* wb = &sm[OWT + ic * 9];
            #pragma unroll
            for (int ky = 0; ky < 3; ++ky)
                #pragma unroll
                for (int kx = 0; kx < 3; ++kx)
                    a += ib[ky * S_T + kx] * wb[ky * 3 + kx];
        }
        lmax = a;
    }
    #pragma unroll
    for (int off = 16; off > 0; off >>= 1)
        lmax = fmaxf(lmax, __shfl_xor_sync(0xffffffffu, lmax, off));
    if (lane == 0) sm[ORED + wid] = lmax;
    __syncthreads();
    if (tid < 32) {
        float v = (tid < NWARP) ? sm[ORED + tid] : -INFINITY;
        #pragma unroll
        for (int off = 16; off > 0; off >>= 1)
            v = fmaxf(v, __shfl_xor_sync(0xffffffffu, v, off));
        if (tid == 0) out[b] = v + cb4[0];
    }
}

// ---------------------------------------------------------------------------
extern "C" void kernel_launch(void* const* d_in, const int* in_sizes, int n_in,
                              void* d_out, int out_size)
{
    cudaFuncSetAttribute(cnn_kernel, cudaFuncAttributeMaxDynamicSharedMemorySize, SMEM_BYTES);

    stats_kernel<<<BTOT, 256>>>(
        (const float*)d_in[0],   // target_scores
        (const float*)d_in[1],   // ptm
        (const float*)d_in[2],   // pmt
        (const float*)d_in[3],   // predicted_iou
        d_in[4]);                // mem_mask (dtype auto-detected)

    cnn_kernel<<<BTOT, TPB, SMEM_BYTES>>>(
        (const float*)d_in[5],  (const float*)d_in[6],
        (const float*)d_in[7],  (const float*)d_in[8],
        (const float*)d_in[9],  (const float*)d_in[10],
        (const float*)d_in[11], (const float*)d_in[12],
        (const float*)d_in[13], (const float*)d_in[14],
        (const float*)d_in[15], (const float*)d_in[16],
        (const float*)d_in[17], (const float*)d_in[18],
        (const float*)d_in[19], (const float*)d_in[20],
        (const float*)d_in[21], (const float*)d_in[22],
        (const float*)d_in[23], (const float*)d_in[24],
        (float*)d_out);
}

// round 9
// speedup vs baseline: 1.6338x; 1.6310x over previous
#include <cuda_runtime.h>
#include <cuda_bf16.h>
#include <mma.h>
#include <math.h>
#include <stdint.h>

using namespace nvcuda;

#define BTOT 512
#define NMEM 30
#define HW 1024
#define NGTH_ 15

typedef unsigned long long u64;

__device__ __forceinline__ u64 dup2f(float v){u64 r;asm("mov.b64 %0,{%1,%1};":"=l"(r):"f"(v));return r;}
__device__ __forceinline__ void fma2(u64&d,u64 a,u64 b){asm("fma.rn.f32x2 %0,%1,%2,%0;":"+l"(d):"l"(a),"l"(b));}
__device__ __forceinline__ float2 unp2(u64 v){float lo,hi;asm("mov.b64 {%0,%1},%2;":"=f"(lo),"=f"(hi):"l"(v));return make_float2(lo,hi);}

__device__ float g_inp6[(size_t)BTOT*6*HW];
__device__ float g_cst[(size_t)BTOT*8];
__device__ float g_x1[(size_t)BTOT*225*64];   // pos-major [p][oc]
__device__ float g_x2[(size_t)BTOT*169*64];
__device__ float g_x3[(size_t)BTOT*121*64];

// ---------------------------------------------------------------------------
// Kernel 1: stats (validated)
// ---------------------------------------------------------------------------
__global__ __launch_bounds__(256) void stats_kernel(
    const float* __restrict__ ts, const float* __restrict__ ptm,
    const float* __restrict__ pmt, const float* __restrict__ piou,
    const void* __restrict__ mask_raw)
{
    const int b = blockIdx.x, tid = threadIdx.x, lane = tid & 31, wid = tid >> 5;
    __shared__ float mf[NMEM], ow[NMEM], pmax[NMEM], warpmax[8], sc[16];

    unsigned int w0 = *(const unsigned int*)mask_raw;
    int mode = (w0 == 1u) ? 1 : ((w0 == 0x3F800000u) ? 2 : 0);

    if (tid == 0) {
        float run = 0.f, ca = 0.f, cg = 0.f, co = 0.f;
        for (int m = 0; m < NMEM; ++m) {
            int idx = b * NMEM + m; float f;
            if (mode == 1)      f = (((const int*)mask_raw)[idx] != 0) ? 1.f : 0.f;
            else if (mode == 2) f = (((const float*)mask_raw)[idx] != 0.f) ? 1.f : 0.f;
            else                f = (((const unsigned char*)mask_raw)[idx] != 0) ? 1.f : 0.f;
            run += f;
            float g = (run - 1.f < (float)NGTH_) ? f : 0.f;
            float o = f - g;
            mf[m] = f; ow[m] = o; ca += f; cg += g; co += o;
        }
        sc[7] = ca; sc[8] = cg; sc[9] = co;
    }

    float tmax = -INFINITY;
    const float* tsb = ts + (size_t)b * HW;
    for (int p = tid; p < HW; p += 256) tmax = fmaxf(tmax, tsb[p]);
    #pragma unroll
    for (int off = 16; off > 0; off >>= 1) tmax = fmaxf(tmax, __shfl_xor_sync(0xffffffffu, tmax, off));
    if (lane == 0) warpmax[wid] = tmax;

    const float* ptmb = ptm + (size_t)b * NMEM * HW;
    for (int m = wid; m < NMEM; m += 8) {
        float mx = -INFINITY;
        const float* pr = ptmb + (size_t)m * HW;
        for (int p = lane; p < HW; p += 32) mx = fmaxf(mx, pr[p]);
        #pragma unroll
        for (int off = 16; off > 0; off >>= 1) mx = fmaxf(mx, __shfl_xor_sync(0xffffffffu, mx, off));
        if (lane == 0) pmax[m] = mx;
    }
    __syncthreads();

    if (wid == 0) {
        float v = (lane < 8) ? warpmax[lane] : -INFINITY;
        #pragma unroll
        for (int off = 4; off > 0; off >>= 1) v = fmaxf(v, __shfl_xor_sync(0xffffffffu, v, off));
        if (lane == 0) sc[0] = v;
    }
    if (wid == 1) {
        float v  = (lane < NMEM) ? pmax[lane] : 0.f;
        float fa = (lane < NMEM) ? mf[lane] : 0.f;
        float fo = (lane < NMEM) ? ow[lane] : 0.f;
        float fg = fa - fo;
        float sa = v*fa, ssa = v*v*fa, sg = v*fg, ssg = v*v*fg, so = v*fo, sso = v*v*fo;
        #pragma unroll
        for (int off = 16; off > 0; off >>= 1) {
            sa  += __shfl_xor_sync(0xffffffffu, sa, off);  ssa += __shfl_xor_sync(0xffffffffu, ssa, off);
            sg  += __shfl_xor_sync(0xffffffffu, sg, off);  ssg += __shfl_xor_sync(0xffffffffu, ssg, off);
            so  += __shfl_xor_sync(0xffffffffu, so, off);  sso += __shfl_xor_sync(0xffffffffu, sso, off);
        }
        if (lane == 0) {
            float ca = sc[7], cg = sc[8], co = sc[9];
            float mA = sa / ca; sc[1] = mA; sc[2] = sqrtf(fmaxf(ssa / ca - mA * mA, 0.f));
            float mG = sg / cg; sc[3] = mG; sc[4] = sqrtf(fmaxf(ssg / cg - mG * mG, 0.f));
            float mO = so / co; sc[5] = mO; sc[6] = sqrtf(fmaxf(sso / co - mO * mO, 0.f));
        }
    }
    __syncthreads();

    if (tid == 0) {
        float* c = g_cst + (size_t)b * 8;
        c[0] = sc[0]; c[1] = piou[b]; c[2] = sc[1]; c[3] = sc[2];
        c[4] = sc[3]; c[5] = sc[4];   c[6] = sc[5]; c[7] = sc[6];
    }

    float* ob = g_inp6 + (size_t)b * 6 * HW;
    const float* pmtb = pmt + (size_t)b * NMEM * HW;
    const float ca = sc[7], co = sc[9];

    for (int p = tid; p < HW; p += 256) {
        float sa = 0, ssa = 0, sg = 0, ssg = 0, so = 0, sso = 0;
        #pragma unroll 5
        for (int m = 0; m < NMEM; ++m) {
            float v = pmtb[(size_t)m * HW + p];
            float fa = mf[m], fo = ow[m];
            sa += v * fa; ssa += v * v * fa;
            if (m < NGTH_) { sg += v; ssg += v * v; }
            so += v * fo; sso += v * v * fo;
        }
        float mA = sa / ca, sA = sqrtf(fmaxf(ssa / ca - mA * mA, 0.f));
        float mG = sg * (1.f / NGTH_), sG = sqrtf(fmaxf(ssg * (1.f / NGTH_) - mG * mG, 0.f));
        float mO = so / co, sO = sqrtf(fmaxf(sso / co - mO * mO, 0.f));
        ob[0*HW+p]=mA; ob[1*HW+p]=sA; ob[2*HW+p]=mG; ob[3*HW+p]=sG; ob[4*HW+p]=mO; ob[5*HW+p]=sO;
    }
}

// ---------------------------------------------------------------------------
// Kernel 2: conv1 + bn + relu + pool -> g_x1 pos-major [225][64]
// ---------------------------------------------------------------------------
#define TPB1 480
__global__ __launch_bounds__(TPB1, 1) void conv1_kernel(
    const float* __restrict__ w1, const float* __restrict__ cb1,
    const float* __restrict__ g1, const float* __restrict__ bb1,
    const float* __restrict__ m1, const float* __restrict__ v1)
{
    __shared__ float sm[6528 + 3456 + 128];
    const int IW_ = 6528, IE_ = 9984;
    const int b = blockIdx.x, tid = threadIdx.x;

    {
        const float* src = g_inp6 + (size_t)b * 6 * HW;
        for (int i = tid; i < 6 * HW; i += TPB1) {
            int c = i >> 10; int rem = i & 1023;
            sm[c * 1088 + (rem >> 5) * 34 + (rem & 31)] = src[i];
        }
        for (int i = tid; i < 64 * 6 * 9; i += TPB1) {
            int oc = i / 54; int r = i - oc * 54;
            int c = r / 9; int t = r - c * 9;
            sm[IW_ + ((oc >> 1) * 6 + c) * 18 + t * 2 + (oc & 1)] = w1[oc * 126 + (c + 2) * 9 + t];
        }
        if (tid < 64) {
            const float* cst = g_cst + (size_t)b * 8;
            float extra = 0.f;
            #pragma unroll
            for (int j = 0; j < 8; ++j) {
                int ic = (j < 2) ? j : (j + 6);
                const float* wb = w1 + tid * 126 + ic * 9;
                float s9 = 0.f;
                #pragma unroll
                for (int t = 0; t < 9; ++t) s9 += wb[t];
                extra += cst[j] * s9;
            }
            float s = g1[tid] * rsqrtf(v1[tid] + 1e-5f);
            sm[IE_ + tid] = s;
            sm[IE_ + 64 + tid] = s * (extra + cb1[tid] - m1[tid]) + bb1[tid];
        }
    }
    __syncthreads();

    float* xo = g_x1 + (size_t)b * 225 * 64;
    #pragma unroll
    for (int itb = 0; itb < 2; ++itb) {
        int it = tid + itb * TPB1;
        int ocg = it / 60;
        int r = it - ocg * 60;
        int pr = r >> 2, pq = r & 3;
        int x0 = 8 * pq, r0 = 2 * pr;

        u64 acc[2][2][8];
        #pragma unroll
        for (int p = 0; p < 2; ++p)
            #pragma unroll
            for (int e = 0; e < 2; ++e)
                #pragma unroll
                for (int c = 0; c < 8; ++c) acc[p][e][c] = 0ull;

        for (int ch = 0; ch < 6; ++ch) {
            const float* ib = &sm[ch * 1088 + r0 * 34 + x0];
            const u64* wb0 = (const u64*)&sm[IW_ + ((ocg * 2) * 6 + ch) * 18];
            const u64* wb1 = (const u64*)&sm[IW_ + ((ocg * 2 + 1) * 6 + ch) * 18];
            #pragma unroll
            for (int ir = 0; ir < 4; ++ir) {
                u64 d[10];
                #pragma unroll
                for (int q = 0; q < 5; ++q) {
                    float2 a = *(const float2*)(ib + ir * 34 + 2 * q);
                    d[2*q] = dup2f(a.x); d[2*q+1] = dup2f(a.y);
                }
                #pragma unroll
                for (int kx = 0; kx < 3; ++kx) {
                    if (ir <= 2) {
                        u64 wa = wb0[ir*3+kx], wc = wb1[ir*3+kx];
                        #pragma unroll
                        for (int c = 0; c < 8; ++c) { fma2(acc[0][0][c], wa, d[c+kx]); fma2(acc[1][0][c], wc, d[c+kx]); }
                    }
                    if (ir >= 1) {
                        u64 wa = wb0[(ir-1)*3+kx], wc = wb1[(ir-1)*3+kx];
                        #pragma unroll
                        for (int c = 0; c < 8; ++c) { fma2(acc[0][1][c], wa, d[c+kx]); fma2(acc[1][1][c], wc, d[c+kx]); }
                    }
                }
            }
        }
        #pragma unroll
        for (int p = 0; p < 2; ++p) {
            int oc0 = ocg * 4 + 2 * p;
            float s0 = sm[IE_+oc0], bi0 = sm[IE_+64+oc0];
            float s1 = sm[IE_+oc0+1], bi1 = sm[IE_+64+oc0+1];
            #pragma unroll
            for (int j = 0; j < 4; ++j) {
                int pt = 4 * pq + j;
                if (pt < 15) {
                    float2 a = unp2(acc[p][0][2*j]), bq = unp2(acc[p][0][2*j+1]);
                    float2 cq = unp2(acc[p][1][2*j]), e = unp2(acc[p][1][2*j+1]);
                    float lo = fmaxf(fmaxf(fmaxf(s0*a.x+bi0,0.f), fmaxf(s0*bq.x+bi0,0.f)),
                                     fmaxf(fmaxf(s0*cq.x+bi0,0.f), fmaxf(s0*e.x+bi0,0.f)));
                    float hi = fmaxf(fmaxf(fmaxf(s1*a.y+bi1,0.f), fmaxf(s1*bq.y+bi1,0.f)),
                                     fmaxf(fmaxf(s1*cq.y+bi1,0.f), fmaxf(s1*e.y+bi1,0.f)));
                    int pos = pr * 15 + pt;
                    xo[pos * 64 + oc0] = lo;
                    xo[pos * 64 + oc0 + 1] = hi;
                }
            }
        }
    }
}

// ---------------------------------------------------------------------------
// Kernel 3/4: conv 64->64 as 9 tap-GEMMs via bf16 wmma (3-pass split)
// ---------------------------------------------------------------------------
template<int IN_W, int OUT_W>
__global__ __launch_bounds__(512, 1) void convmma_kernel(
    const float* __restrict__ xin_base, float* __restrict__ xout_base,
    const float* __restrict__ wsrc, const float* __restrict__ cb,
    const float* __restrict__ gg, const float* __restrict__ bbv,
    const float* __restrict__ mmv, const float* __restrict__ vvv)
{
    constexpr int INROWS = IN_W * IN_W;
    constexpr int MMAX = (OUT_W - 1) * IN_W + OUT_W;
    constexpr int MTILES = (MMAX + 15) / 16;
    constexpr int XROWS = ((MTILES * 16 + 2 * IN_W + 2 + 15) / 16) * 16;
    constexpr int NUNITS = MTILES * 2;
    constexpr int LDX = 72;
    constexpr int OXH = 0;
    constexpr int OXL = OXH + XROWS * LDX * 2;
    constexpr int OWH = OXL + XROWS * LDX * 2;
    constexpr int OWL = OWH + 64 * LDX * 2;
    constexpr int OSB = OWL + 64 * LDX * 2;
    constexpr int OPATCH = OSB + 512;

    extern __shared__ char smc[];
    __nv_bfloat16* Xh = (__nv_bfloat16*)(smc + OXH);
    __nv_bfloat16* Xl = (__nv_bfloat16*)(smc + OXL);
    __nv_bfloat16* Wh = (__nv_bfloat16*)(smc + OWH);
    __nv_bfloat16* Wl = (__nv_bfloat16*)(smc + OWL);
    float* sbs = (float*)(smc + OSB);

    const int b = blockIdx.x, tid = threadIdx.x, wid = tid >> 5, lane = tid & 31;
    const float* xin = xin_base + (size_t)b * INROWS * 64;
    float* xout = xout_base + (size_t)b * OUT_W * OUT_W * 64;

    for (int i = tid; i < INROWS * 64; i += 512) {
        int p = i >> 6, c = i & 63;
        float v = xin[i];
        __nv_bfloat16 h = __float2bfloat16(v);
        __nv_bfloat16 l = __float2bfloat16(v - __bfloat162float(h));
        Xh[p * LDX + c] = h; Xl[p * LDX + c] = l;
    }
    for (int i = tid; i < (XROWS - INROWS) * 64; i += 512) {
        int p = INROWS + (i >> 6), c = i & 63;
        Xh[p * LDX + c] = __float2bfloat16(0.f);
        Xl[p * LDX + c] = __float2bfloat16(0.f);
    }
    if (tid < 64) {
        float s = gg[tid] * rsqrtf(vvv[tid] + 1e-5f);
        sbs[tid] = s;
        sbs[64 + tid] = s * (cb[tid] - mmv[tid]) + bbv[tid];
    }

    wmma::fragment<wmma::accumulator, 16, 16, 16, float> acc[2][2];
    #pragma unroll
    for (int u = 0; u < 2; ++u)
        #pragma unroll
        for (int n = 0; n < 2; ++n)
            wmma::fill_fragment(acc[u][n], 0.f);

    for (int tap = 0; tap < 9; ++tap) {
        __syncthreads();
        for (int i = tid; i < 4096; i += 512) {
            int oc = i >> 6, ic = i & 63;
            float v = wsrc[oc * 576 + ic * 9 + tap];
            __nv_bfloat16 h = __float2bfloat16(v);
            __nv_bfloat16 l = __float2bfloat16(v - __bfloat162float(h));
            Wh[ic * LDX + oc] = h; Wl[ic * LDX + oc] = l;
        }
        __syncthreads();

        int ky = tap / 3, kx = tap - (tap / 3) * 3;
        int toff = ky * IN_W + kx;
        #pragma unroll
        for (int un = 0; un < 2; ++un) {
            int u = wid + 16 * un;
            if (u < NUNITS) {
                int mt = u >> 1, nh = u & 1;
                const __nv_bfloat16* A0 = Xh + (mt * 16 + toff) * LDX;
                const __nv_bfloat16* A1 = Xl + (mt * 16 + toff) * LDX;
                #pragma unroll
                for (int k = 0; k < 4; ++k) {
                    wmma::fragment<wmma::matrix_a, 16, 16, 16, __nv_bfloat16, wmma::row_major> ah, al;
                    wmma::load_matrix_sync(ah, A0 + k * 16, LDX);
                    wmma::load_matrix_sync(al, A1 + k * 16, LDX);
                    #pragma unroll
                    for (int nt = 0; nt < 2; ++nt) {
                        wmma::fragment<wmma::matrix_b, 16, 16, 16, __nv_bfloat16, wmma::row_major> bh, bl;
                        wmma::load_matrix_sync(bh, Wh + k * 16 * LDX + nh * 32 + nt * 16, LDX);
                        wmma::load_matrix_sync(bl, Wl + k * 16 * LDX + nh * 32 + nt * 16, LDX);
                        wmma::mma_sync(acc[un][nt], ah, bh, acc[un][nt]);
                        wmma::mma_sync(acc[un][nt], ah, bl, acc[un][nt]);
                        wmma::mma_sync(acc[un][nt], al, bh, acc[un][nt]);
                    }
                }
            }
        }
    }

    float* patch = (float*)(smc + OPATCH) + wid * 16 * 36;
    #pragma unroll
    for (int un = 0; un < 2; ++un) {
        int u = wid + 16 * un;
        if (u < NUNITS) {
            int mt = u >> 1, nh = u & 1;
            wmma::store_matrix_sync(patch,      acc[un][0], 36, wmma::mem_row_major);
            wmma::store_matrix_sync(patch + 16, acc[un][1], 36, wmma::mem_row_major);
            __syncwarp();
            int r = lane & 15, ch = (lane >> 4) * 16;
            int p = mt * 16 + r;
            int y = p / IN_W, x = p - y * IN_W;
            if (y < OUT_W && x < OUT_W) {
                int orow = y * OUT_W + x;
                #pragma unroll
                for (int j = 0; j < 16; ++j) {
                    int c = nh * 32 + ch + j;
                    float v = patch[r * 36 + ch + j];
                    xout[orow * 64 + c] = fmaxf(sbs[c] * v + sbs[64 + c], 0.f);
                }
            }
            __syncwarp();
        }
    }
}

// ---------------------------------------------------------------------------
// Kernel 5: conv4 (64->1) + global max
// ---------------------------------------------------------------------------
__global__ __launch_bounds__(128) void conv4_kernel(
    const float* __restrict__ w4, const float* __restrict__ cb4, float* __restrict__ out)
{
    __shared__ float xs[121 * 68];
    __shared__ float ws[576];
    __shared__ float red[4];
    const int b = blockIdx.x, tid = threadIdx.x;
    const float* src = g_x3 + (size_t)b * 121 * 64;
    for (int i = tid; i < 121 * 64; i += 128) xs[(i >> 6) * 68 + (i & 63)] = src[i];
    for (int i = tid; i < 576; i += 128) ws[i] = w4[i];
    __syncthreads();

    float lm = -INFINITY;
    if (tid < 81) {
        int y = tid / 9, x = tid - (tid / 9) * 9;
        float a = 0.f;
        #pragma unroll
        for (int ky = 0; ky < 3; ++ky)
            #pragma unroll
            for (int kx = 0; kx < 3; ++kx) {
                const float* row = xs + ((y + ky) * 11 + (x + kx)) * 68;
                int t = ky * 3 + kx;
                for (int ic = 0; ic < 64; ++ic)
                    a += row[ic] * ws[ic * 9 + t];
            }
        lm = a;
    }
    #pragma unroll
    for (int off = 16; off > 0; off >>= 1) lm = fmaxf(lm, __shfl_xor_sync(0xffffffffu, lm, off));
    if ((tid & 31) == 0) red[tid >> 5] = lm;
    __syncthreads();
    if (tid == 0) {
        float v = fmaxf(fmaxf(red[0], red[1]), fmaxf(red[2], red[3]));
        out[b] = v + cb4[0];
    }
}

// ---------------------------------------------------------------------------
extern "C" void kernel_launch(void* const* d_in, const int* in_sizes, int n_in,
                              void* d_out, int out_size)
{
    const int S2 = 124928;
    const int S3 = 106496;
    static float *p1 = nullptr, *p2 = nullptr, *p3 = nullptr;
    if (!p1) {
        cudaGetSymbolAddress((void**)&p1, g_x1);
        cudaGetSymbolAddress((void**)&p2, g_x2);
        cudaGetSymbolAddress((void**)&p3, g_x3);
        cudaFuncSetAttribute(convmma_kernel<15,13>, cudaFuncAttributeMaxDynamicSharedMemorySize, S2);
        cudaFuncSetAttribute(convmma_kernel<13,11>, cudaFuncAttributeMaxDynamicSharedMemorySize, S3);
    }

    stats_kernel<<<BTOT, 256>>>(
        (const float*)d_in[0], (const float*)d_in[1],
        (const float*)d_in[2], (const float*)d_in[3], d_in[4]);

    conv1_kernel<<<BTOT, TPB1>>>(
        (const float*)d_in[5],  (const float*)d_in[6],
        (const float*)d_in[7],  (const float*)d_in[8],
        (const float*)d_in[9],  (const float*)d_in[10]);

    convmma_kernel<15,13><<<BTOT, 512, S2>>>(
        p1, p2,
        (const float*)d_in[11], (const float*)d_in[12],
        (const float*)d_in[13], (const float*)d_in[14],
        (const float*)d_in[15], (const float*)d_in[16]);

    convmma_kernel<13,11><<<BTOT, 512, S3>>>(
        p2, p3,
        (const float*)d_in[17], (const float*)d_in[18],
        (const float*)d_in[19], (const float*)d_in[20],
        (const float*)d_in[21], (const float*)d_in[22]);

    conv4_kernel<<<BTOT, 128>>>(
        (const float*)d_in[23], (const float*)d_in[24], (float*)d_out);
}